// round 1
// baseline (speedup 1.0000x reference)
#include <cuda_runtime.h>
#include <cuda_bf16.h>

#define B 512
#define T 256
#define C 384
#define HS 64
#define BT (B * T)

// ---------------- scratch (static device globals; no allocation) ------------
__device__ float g_Q[BT * HS];
__device__ float g_K[BT * HS];
__device__ float g_V[BT * HS];

// ---------------- QKV projection: O[BT,64] = X[BT,384] @ W[384,64] ----------
// CTA tile: 128 rows x 64 cols, K-chunks of 32. 256 threads, 8x4 micro-tile.
__global__ __launch_bounds__(256) void qkv_gemm(
    const float* __restrict__ x,
    const float* __restrict__ Wq,
    const float* __restrict__ Wk,
    const float* __restrict__ Wv)
{
    const float* W = (blockIdx.y == 0) ? Wq : ((blockIdx.y == 1) ? Wk : Wv);
    float* O       = (blockIdx.y == 0) ? g_Q : ((blockIdx.y == 1) ? g_K : g_V);

    const int rowBase = blockIdx.x * 128;
    const int tid  = threadIdx.x;
    const int tcol = tid & 15;   // 16 col-groups * 4 cols = 64
    const int trow = tid >> 4;   // 16 row-groups * 8 rows = 128

    __shared__ float xs[128][32];
    __shared__ float ws[32][64];

    float acc[8][4];
#pragma unroll
    for (int r = 0; r < 8; r++)
#pragma unroll
        for (int c = 0; c < 4; c++) acc[r][c] = 0.0f;

    for (int k0 = 0; k0 < C; k0 += 32) {
        // load x tile: 128x32 = 1024 float4, 4 per thread
#pragma unroll
        for (int t = 0; t < 4; t++) {
            int f = tid + t * 256;
            int r = f >> 3;          // 8 float4 per row
            int c4 = f & 7;
            float4 v = *(const float4*)(x + (size_t)(rowBase + r) * C + k0 + c4 * 4);
            *(float4*)(&xs[r][c4 * 4]) = v;
        }
        // load W tile: 32x64 = 512 float4, 2 per thread
#pragma unroll
        for (int t = 0; t < 2; t++) {
            int f = tid + t * 256;
            int r = f >> 4;          // 16 float4 per row
            int c4 = f & 15;
            *(float4*)(&ws[r][c4 * 4]) =
                *(const float4*)(W + (size_t)(k0 + r) * HS + c4 * 4);
        }
        __syncthreads();

#pragma unroll
        for (int kk = 0; kk < 32; kk++) {
            float a[8];
#pragma unroll
            for (int r = 0; r < 8; r++) a[r] = xs[trow * 8 + r][kk];
            float4 b = *(const float4*)(&ws[kk][tcol * 4]);
#pragma unroll
            for (int r = 0; r < 8; r++) {
                acc[r][0] += a[r] * b.x;
                acc[r][1] += a[r] * b.y;
                acc[r][2] += a[r] * b.z;
                acc[r][3] += a[r] * b.w;
            }
        }
        __syncthreads();
    }

#pragma unroll
    for (int r = 0; r < 8; r++) {
        float4 v = make_float4(acc[r][0], acc[r][1], acc[r][2], acc[r][3]);
        *(float4*)(O + (size_t)(rowBase + trow * 8 + r) * HS + tcol * 4) = v;
    }
}

// ---------------- causal attention: one CTA per batch -----------------------
// K,V tiles in dynamic smem (128 KB); one query row per thread.
// Softmax without max-subtraction: scores ~ N(0,1) scale, exp is safe in fp32
// and the result is mathematically identical to softmax.
__global__ __launch_bounds__(256, 1) void attn(float* __restrict__ out)
{
    extern __shared__ float smem[];
    float4* ks4 = (float4*)smem;                 // 256*64 floats = 4096 float4
    float4* vs4 = (float4*)(smem + T * HS);      // another 4096 float4

    const int b   = blockIdx.x;
    const int tid = threadIdx.x;

    const float4* Kg = (const float4*)(g_K + (size_t)b * T * HS);
    const float4* Vg = (const float4*)(g_V + (size_t)b * T * HS);
#pragma unroll
    for (int t = 0; t < 16; t++) {
        ks4[tid + t * 256] = Kg[tid + t * 256];
        vs4[tid + t * 256] = Vg[tid + t * 256];
    }
    __syncthreads();

    const int i = tid;  // query row
    float q[64];
    {
        const float4* Qg = (const float4*)(g_Q + ((size_t)b * T + i) * HS);
#pragma unroll
        for (int h4 = 0; h4 < 16; h4++) {
            float4 v = Qg[h4];
            q[4 * h4 + 0] = v.x; q[4 * h4 + 1] = v.y;
            q[4 * h4 + 2] = v.z; q[4 * h4 + 3] = v.w;
        }
    }

    float acc[64];
#pragma unroll
    for (int h = 0; h < 64; h++) acc[h] = 0.0f;
    float l = 0.0f;

    const float scale = 0.125f;  // HS^-0.5 = 1/8

    for (int j = 0; j <= i; j++) {
        const float4* kr = ks4 + j * 16;
        float s0 = 0.f, s1 = 0.f, s2 = 0.f, s3 = 0.f;
#pragma unroll
        for (int h4 = 0; h4 < 16; h4++) {
            float4 kv = kr[h4];
            s0 += q[4 * h4 + 0] * kv.x;
            s1 += q[4 * h4 + 1] * kv.y;
            s2 += q[4 * h4 + 2] * kv.z;
            s3 += q[4 * h4 + 3] * kv.w;
        }
        float s = ((s0 + s1) + (s2 + s3)) * scale;
        float p = expf(s);
        l += p;
        const float4* vr = vs4 + j * 16;
#pragma unroll
        for (int h4 = 0; h4 < 16; h4++) {
            float4 vv = vr[h4];
            acc[4 * h4 + 0] += p * vv.x;
            acc[4 * h4 + 1] += p * vv.y;
            acc[4 * h4 + 2] += p * vv.z;
            acc[4 * h4 + 3] += p * vv.w;
        }
    }

    const float inv = 1.0f / l;
    float4* og = (float4*)(out + ((size_t)b * T + i) * HS);
#pragma unroll
    for (int h4 = 0; h4 < 16; h4++) {
        og[h4] = make_float4(acc[4 * h4 + 0] * inv, acc[4 * h4 + 1] * inv,
                             acc[4 * h4 + 2] * inv, acc[4 * h4 + 3] * inv);
    }
}

// ---------------- launch -----------------------------------------------------
extern "C" void kernel_launch(void* const* d_in, const int* in_sizes, int n_in,
                              void* d_out, int out_size)
{
    (void)in_sizes; (void)n_in; (void)out_size;
    const float* x  = (const float*)d_in[0];
    const float* Wq = (const float*)d_in[1];
    const float* Wk = (const float*)d_in[2];
    const float* Wv = (const float*)d_in[3];
    float* out = (float*)d_out;

    dim3 gemm_grid(BT / 128, 3);
    qkv_gemm<<<gemm_grid, 256>>>(x, Wq, Wk, Wv);

    const int smem_bytes = 2 * T * HS * sizeof(float);  // 128 KB
    cudaFuncSetAttribute(attn, cudaFuncAttributeMaxDynamicSharedMemorySize,
                         smem_bytes);
    attn<<<B, 256, smem_bytes>>>(out);
}

// round 3
// speedup vs baseline: 1.0036x; 1.0036x over previous
#include <cuda_runtime.h>
#include <cuda_bf16.h>
#include <mma.h>
#include <cstdint>
#include <cstring>

using namespace nvcuda;

#define B 512
#define T 256
#define C 384
#define HS 64
#define BT (B * T)

// ---------------- scratch (static device globals; no allocation) ------------
__device__ float g_Q[BT * HS];
__device__ float g_K[BT * HS];
__device__ float g_V[BT * HS];
// bf16 split weights, [k][n] row-major, n in [0,192) = [Wq|Wk|Wv] columns
__device__ __nv_bfloat16 g_Whi[C * 192];
__device__ __nv_bfloat16 g_Wlo[C * 192];

// ---------------- W bf16 split kernel ----------------------------------------
__global__ void convert_w(const float* __restrict__ Wq,
                          const float* __restrict__ Wk,
                          const float* __restrict__ Wv)
{
    int k = blockIdx.x;     // 0..383
    int n = threadIdx.x;    // 0..191
    const float* W = (n < 64) ? Wq : ((n < 128) ? Wk : Wv);
    float w = W[(size_t)k * HS + (n & 63)];
    __nv_bfloat16 hi = __float2bfloat16(w);
    float rem = w - __bfloat162float(hi);
    __nv_bfloat16 lo = __float2bfloat16(rem);
    g_Whi[(size_t)k * 192 + n] = hi;
    g_Wlo[(size_t)k * 192 + n] = lo;
}

// ---------------- QKV GEMM via WMMA bf16 (2-term split) ----------------------
// CTA: 256 threads = 8 warps; tile M=128 x N=192; K in 6 chunks of 64.
// Warp grid 4(M) x 2(N): warp tile 32x96 = 2x6 fragments of 16x16.
static constexpr int A_LD = 72;                    // padded bf16 row (144B, 16B-mult)
static constexpr int SA_HI = 0;                    // 128*72*2 = 18432
static constexpr int SA_LO = 18432;
static constexpr int SB_HI = 36864;                // 64*192*2 = 24576
static constexpr int SB_LO = 61440;
static constexpr int GEMM_SMEM_TOTAL = 86016;

__global__ __launch_bounds__(256) void qkv_gemm_wmma(const float* __restrict__ x)
{
    extern __shared__ char smem[];
    __nv_bfloat16* Ahi = (__nv_bfloat16*)(smem + SA_HI);
    __nv_bfloat16* Alo = (__nv_bfloat16*)(smem + SA_LO);
    __nv_bfloat16* Bhi = (__nv_bfloat16*)(smem + SB_HI);
    __nv_bfloat16* Blo = (__nv_bfloat16*)(smem + SB_LO);

    const int tid = threadIdx.x;
    const int wid = tid >> 5;
    const int warp_m = wid >> 1;       // 0..3 -> row offset 32*warp_m
    const int warp_n = wid & 1;        // 0..1 -> col offset 96*warp_n
    const int rowBase = blockIdx.x * 128;

    wmma::fragment<wmma::accumulator, 16, 16, 16, float> acc[2][6];
#pragma unroll
    for (int i = 0; i < 2; i++)
#pragma unroll
        for (int j = 0; j < 6; j++) wmma::fill_fragment(acc[i][j], 0.0f);

    for (int kc = 0; kc < 6; kc++) {
        const int k0 = kc * 64;

        // --- x chunk [128 x 64] fp32 -> hi/lo bf16 smem; 2048 float4, 8/thread
#pragma unroll
        for (int t = 0; t < 8; t++) {
            int f = tid + t * 256;
            int r = f >> 4;          // 16 float4 per row
            int c4 = f & 15;
            float4 v = *(const float4*)(x + (size_t)(rowBase + r) * C + k0 + c4 * 4);
            __nv_bfloat16 h0 = __float2bfloat16(v.x);
            __nv_bfloat16 h1 = __float2bfloat16(v.y);
            __nv_bfloat16 h2 = __float2bfloat16(v.z);
            __nv_bfloat16 h3 = __float2bfloat16(v.w);
            __nv_bfloat16 l0 = __float2bfloat16(v.x - __bfloat162float(h0));
            __nv_bfloat16 l1 = __float2bfloat16(v.y - __bfloat162float(h1));
            __nv_bfloat16 l2 = __float2bfloat16(v.z - __bfloat162float(h2));
            __nv_bfloat16 l3 = __float2bfloat16(v.w - __bfloat162float(h3));
            __nv_bfloat16* ah = Ahi + r * A_LD + c4 * 4;
            __nv_bfloat16* al = Alo + r * A_LD + c4 * 4;
            ah[0] = h0; ah[1] = h1; ah[2] = h2; ah[3] = h3;
            al[0] = l0; al[1] = l1; al[2] = l2; al[3] = l3;
        }

        // --- W chunk [64 x 192] bf16 hi/lo from global; 1536 uint4, 6/thread
#pragma unroll
        for (int t = 0; t < 6; t++) {
            int f = tid + t * 256;
            int r = f / 24;          // 24 uint4 (192 bf16) per row
            int u = f - r * 24;
            const uint4* src_h = (const uint4*)(g_Whi + (size_t)(k0 + r) * 192) + u;
            const uint4* src_l = (const uint4*)(g_Wlo + (size_t)(k0 + r) * 192) + u;
            *((uint4*)(Bhi + (size_t)r * 192) + u) = *src_h;
            *((uint4*)(Blo + (size_t)r * 192) + u) = *src_l;
        }
        __syncthreads();

#pragma unroll
        for (int ks = 0; ks < 4; ks++) {
            wmma::fragment<wmma::matrix_a, 16, 16, 16, __nv_bfloat16, wmma::row_major> ah[2], al[2];
#pragma unroll
            for (int i = 0; i < 2; i++) {
                const __nv_bfloat16* pa = Ahi + (warp_m * 32 + i * 16) * A_LD + ks * 16;
                const __nv_bfloat16* pl = Alo + (warp_m * 32 + i * 16) * A_LD + ks * 16;
                wmma::load_matrix_sync(ah[i], pa, A_LD);
                wmma::load_matrix_sync(al[i], pl, A_LD);
            }
#pragma unroll
            for (int j = 0; j < 6; j++) {
                int col = warp_n * 96 + j * 16;
                wmma::fragment<wmma::matrix_b, 16, 16, 16, __nv_bfloat16, wmma::row_major> bh, bl;
                wmma::load_matrix_sync(bh, Bhi + ks * 16 * 192 + col, 192);
                wmma::load_matrix_sync(bl, Blo + ks * 16 * 192 + col, 192);
#pragma unroll
                for (int i = 0; i < 2; i++) {
                    wmma::mma_sync(acc[i][j], ah[i], bh, acc[i][j]);
                    wmma::mma_sync(acc[i][j], ah[i], bl, acc[i][j]);
                    wmma::mma_sync(acc[i][j], al[i], bh, acc[i][j]);
                }
            }
        }
        __syncthreads();
    }

    // --- epilogue: store to g_Q / g_K / g_V -----------------------------------
#pragma unroll
    for (int i = 0; i < 2; i++) {
#pragma unroll
        for (int j = 0; j < 6; j++) {
            int col = warp_n * 96 + j * 16;
            float* dst = (col < 64) ? g_Q : ((col < 128) ? g_K : g_V);
            int c = col & 63;
            int row = rowBase + warp_m * 32 + i * 16;
            wmma::store_matrix_sync(dst + (size_t)row * HS + c, acc[i][j], HS,
                                    wmma::mem_row_major);
        }
    }
}

// ---------------- causal attention: one CTA per batch (unchanged) ------------
__global__ __launch_bounds__(256, 1) void attn(float* __restrict__ out)
{
    extern __shared__ float smemf[];
    float4* ks4 = (float4*)smemf;
    float4* vs4 = (float4*)(smemf + T * HS);

    const int b   = blockIdx.x;
    const int tid = threadIdx.x;

    const float4* Kg = (const float4*)(g_K + (size_t)b * T * HS);
    const float4* Vg = (const float4*)(g_V + (size_t)b * T * HS);
#pragma unroll
    for (int t = 0; t < 16; t++) {
        ks4[tid + t * 256] = Kg[tid + t * 256];
        vs4[tid + t * 256] = Vg[tid + t * 256];
    }
    __syncthreads();

    const int i = tid;
    float q[64];
    {
        const float4* Qg = (const float4*)(g_Q + ((size_t)b * T + i) * HS);
#pragma unroll
        for (int h4 = 0; h4 < 16; h4++) {
            float4 v = Qg[h4];
            q[4 * h4 + 0] = v.x; q[4 * h4 + 1] = v.y;
            q[4 * h4 + 2] = v.z; q[4 * h4 + 3] = v.w;
        }
    }

    float acc[64];
#pragma unroll
    for (int h = 0; h < 64; h++) acc[h] = 0.0f;
    float l = 0.0f;
    const float scale = 0.125f;

    for (int j = 0; j <= i; j++) {
        const float4* kr = ks4 + j * 16;
        float s0 = 0.f, s1 = 0.f, s2 = 0.f, s3 = 0.f;
#pragma unroll
        for (int h4 = 0; h4 < 16; h4++) {
            float4 kv = kr[h4];
            s0 += q[4 * h4 + 0] * kv.x;
            s1 += q[4 * h4 + 1] * kv.y;
            s2 += q[4 * h4 + 2] * kv.z;
            s3 += q[4 * h4 + 3] * kv.w;
        }
        float s = ((s0 + s1) + (s2 + s3)) * scale;
        float p = expf(s);
        l += p;
        const float4* vr = vs4 + j * 16;
#pragma unroll
        for (int h4 = 0; h4 < 16; h4++) {
            float4 vv = vr[h4];
            acc[4 * h4 + 0] += p * vv.x;
            acc[4 * h4 + 1] += p * vv.y;
            acc[4 * h4 + 2] += p * vv.z;
            acc[4 * h4 + 3] += p * vv.w;
        }
    }

    const float inv = 1.0f / l;
    float4* og = (float4*)(out + ((size_t)b * T + i) * HS);
#pragma unroll
    for (int h4 = 0; h4 < 16; h4++) {
        og[h4] = make_float4(acc[4 * h4 + 0] * inv, acc[4 * h4 + 1] * inv,
                             acc[4 * h4 + 2] * inv, acc[4 * h4 + 3] * inv);
    }
}

// ---------------- launch ------------------------------------------------------
extern "C" void kernel_launch(void* const* d_in, const int* in_sizes, int n_in,
                              void* d_out, int out_size)
{
    (void)in_sizes; (void)n_in; (void)out_size;
    const float* x  = (const float*)d_in[0];
    const float* Wq = (const float*)d_in[1];
    const float* Wk = (const float*)d_in[2];
    const float* Wv = (const float*)d_in[3];
    float* out = (float*)d_out;

    convert_w<<<C, 192>>>(Wq, Wk, Wv);

    cudaFuncSetAttribute(qkv_gemm_wmma, cudaFuncAttributeMaxDynamicSharedMemorySize,
                         GEMM_SMEM_TOTAL);
    qkv_gemm_wmma<<<BT / 128, 256, GEMM_SMEM_TOTAL>>>(x);

    const int attn_smem = 2 * T * HS * sizeof(float);  // 128 KB
    cudaFuncSetAttribute(attn, cudaFuncAttributeMaxDynamicSharedMemorySize,
                         attn_smem);
    attn<<<B, 256, attn_smem>>>(out);
}